// round 1
// baseline (speedup 1.0000x reference)
#include <cuda_runtime.h>

#define LROWS  8192
#define NCOLS  8
#define NB     64
#define NT     256
#define EPT    4          // elements per thread: NB*NT*EPT = 65536 = LROWS*NCOLS
#define NITERS 200

// err = 2^(-2*bits), bits = {2,3,4,5,6,8,10,12}
__constant__ float c_err[8] = {
    6.25e-2f, 1.5625e-2f, 3.90625e-3f, 9.765625e-4f,
    2.44140625e-4f, 1.52587890625e-5f, 9.5367431640625e-7f, 5.9604644775390625e-8f
};

__device__ float    g_sum_n;              // sum(n) = 1e5*sum(n_raw) + 1e3*L
__device__ float    g_inv_sens;           // 1/(sum(sens_raw)+1e-12)
__device__ unsigned g_count;              // barrier arrival counter (monotonic per launch)
__device__ float    g_colsum[4][NCOLS * 16]; // ring of 4 slots, 64B stride per column

// ---------------------------------------------------------------------------
// Pre-kernel: input sums + barrier/ring reset (makes graph replays deterministic)
// ---------------------------------------------------------------------------
__global__ void da_pre_kernel(const float* __restrict__ n_raw,
                              const float* __restrict__ sens_raw) {
    __shared__ float s1[NT / 32], s2[NT / 32];
    int t = threadIdx.x;
    float sn = 0.f, ss = 0.f;
    for (int i = t; i < LROWS; i += NT) { sn += n_raw[i]; ss += sens_raw[i]; }
#pragma unroll
    for (int o = 16; o; o >>= 1) {
        sn += __shfl_xor_sync(0xffffffffu, sn, o);
        ss += __shfl_xor_sync(0xffffffffu, ss, o);
    }
    if ((t & 31) == 0) { s1[t >> 5] = sn; s2[t >> 5] = ss; }
    __syncthreads();
    if (t == 0) {
        float a = 0.f, b = 0.f;
#pragma unroll
        for (int w = 0; w < NT / 32; w++) { a += s1[w]; b += s2[w]; }
        g_sum_n    = a * 1e5f + 1e3f * (float)LROWS;
        g_inv_sens = 1.0f / (b + 1e-12f);
        g_count    = 0u;
#pragma unroll
        for (int s = 0; s < 4; s++)
#pragma unroll
            for (int c = 0; c < NCOLS; c++) g_colsum[s][c * 16] = 0.f;
    }
}

// ---------------------------------------------------------------------------
// Main persistent Sinkhorn kernel. 64 blocks x 256 threads (all co-resident).
// Lane layout: col = lane&7, rowgroup = lane>>3 (4 rows per warp per step).
// ---------------------------------------------------------------------------
__global__ void __launch_bounds__(NT, 1)
da_sinkhorn_kernel(const float* __restrict__ theta,
                   const float* __restrict__ phi,
                   const float* __restrict__ sens_raw,
                   const float* __restrict__ n_raw,
                   float* __restrict__ out) {
    const int      tid  = threadIdx.x;
    const int      lane = tid & 31;
    const int      warp = tid >> 5;
    const int      col  = lane & 7;
    const int      rg   = lane >> 3;
    const int      wg   = blockIdx.x * (NT / 32) + warp;   // global warp id 0..511
    const int      rowBase = wg * (EPT * 4) + rg;
    const unsigned FULL = 0xffffffffu;

    const float inv_sumn = 1.0f / g_sum_n;
    const float inv_sens = g_inv_sens;

    // log_b[col] = phi[col] - logsumexp(phi)
    float lb;
    {
        float p[8];
#pragma unroll
        for (int j = 0; j < 8; j++) p[j] = phi[j];
        float m = p[0];
#pragma unroll
        for (int j = 1; j < 8; j++) m = fmaxf(m, p[j]);
        float s = 0.f;
#pragma unroll
        for (int j = 0; j < 8; j++) s += __expf(p[j] - m);
        lb = p[col] - m - __logf(s);
    }

    // Load K tile + row marginals into registers
    float K[EPT], a[EPT];
#pragma unroll
    for (int e = 0; e < EPT; e++) {
        int   row = rowBase + e * 4;
        float n   = n_raw[row] * 1e5f + 1e3f;
        a[e]      = n * inv_sumn;
        float C   = n * (sens_raw[row] * inv_sens) * c_err[col];
        K[e]      = (theta[row * 8 + col] - C) * 50.0f;   // -(C-theta)/eps, eps=0.02
    }

    __shared__ float sred[NT / 32][8];

    float g = 0.0f;
    float p[EPT];
    float Tlast = 1.0f, gd = 0.0f;

    for (int it = 0; it < NITERS; ++it) {
        const int slot = it & 3;

        // ---- f-step (row LSE over 8 cols) + column partials, all in registers
        float colsum = 0.0f;
#pragma unroll
        for (int e = 0; e < EPT; e++) {
            float x = K[e] + g;
            float m = x;
            m = fmaxf(m, __shfl_xor_sync(FULL, m, 1));
            m = fmaxf(m, __shfl_xor_sync(FULL, m, 2));
            m = fmaxf(m, __shfl_xor_sync(FULL, m, 4));
            float E = __expf(x - m);
            float S = E;
            S += __shfl_xor_sync(FULL, S, 1);
            S += __shfl_xor_sync(FULL, S, 2);
            S += __shfl_xor_sync(FULL, S, 4);
            // P_ij = exp(K+f+g_old) = E * (a/S)   (exp(f+m) = a/S, no log/exp needed)
            p[e]   = E * __fdividef(a[e], S);
            colsum += p[e];
        }
        // warp column reduce (rows within warp)
        colsum += __shfl_xor_sync(FULL, colsum, 8);
        colsum += __shfl_xor_sync(FULL, colsum, 16);

        // ---- block combine
        if (lane < 8) sred[warp][col] = colsum;
        __syncthreads();
        if (tid < 8) {
            float t = 0.f;
#pragma unroll
            for (int w = 0; w < NT / 32; w++) t += sred[w][tid];
            atomicAdd(&g_colsum[slot][tid * 16], t);
            __threadfence();           // make column atomics + ring zeroes gpu-visible
        }
        __syncthreads();

        // ---- grid barrier: monotonic count, acquire-spin
        if (tid == 0) {
            atomicAdd(&g_count, 1u);
            const unsigned target = (unsigned)(it + 1) * NB;
            unsigned v;
            do {
                asm volatile("ld.acquire.gpu.u32 %0, [%1];"
                             : "=r"(v) : "l"(&g_count) : "memory");
            } while (v < target);
        }
        __syncthreads();

        // ---- read global column sums (L2, bypass L1), update g
        float T  = fmaxf(__ldcg(&g_colsum[slot][col * 16]), 1e-35f);
        float gn = lb + g - __logf(T);
        gd    = gn - g;
        g     = gn;
        Tlast = T;

        // zero ring slot for reuse at iteration it+2 (fenced at next barrier)
        if (tid < 8) __stcg(&g_colsum[(slot + 2) & 3][tid * 16], 0.0f);
        __syncthreads();   // keep sred reuse safe across iterations
    }

    // ---- final plan: P = p * exp(g_new - g_old); total = sum_j T_j*exp(dg_j)
    float ed = __expf(gd);
    float tg = Tlast * ed;
    tg += __shfl_xor_sync(FULL, tg, 1);
    tg += __shfl_xor_sync(FULL, tg, 2);
    tg += __shfl_xor_sync(FULL, tg, 4);
    float inv = 1.0f / (tg + 1e-40f);

#pragma unroll
    for (int e = 0; e < EPT; e++) {
        int row = rowBase + e * 4;
        out[row * 8 + col] = p[e] * ed * inv;
    }
}

// ---------------------------------------------------------------------------
extern "C" void kernel_launch(void* const* d_in, const int* in_sizes, int n_in,
                              void* d_out, int out_size) {
    const float* theta    = (const float*)d_in[0];
    const float* phi      = (const float*)d_in[1];
    const float* sens_raw = (const float*)d_in[2];
    const float* n_raw    = (const float*)d_in[3];
    float*       out      = (float*)d_out;

    da_pre_kernel<<<1, NT>>>(n_raw, sens_raw);
    da_sinkhorn_kernel<<<NB, NT>>>(theta, phi, sens_raw, n_raw, out);
}